// round 10
// baseline (speedup 1.0000x reference)
#include <cuda_runtime.h>
#include <cstdint>

#define SEQ  2048
#define D    300
#define U    150
#define G4   600
#define H1   300
#define NSYN 4
#define TT   8
#define TTP  16

#define CS   10    // cluster size (CTAs per direction)
#define UPC  15    // units per CTA
#define KQ   40    // k-rows per quarter (4*40 = 160 = 150 + 10 zero pad)

__device__ float g_zx_f[SEQ * G4];
__device__ float g_zx_b[SEQ * G4];
__device__ float g_hidden[SEQ * H1];
__device__ float g_out[SEQ * H1];
__device__ float g_hhat[SEQ * H1];
__device__ float g_c2[SEQ];
__device__ float g_H[H1];

__device__ __forceinline__ float tanh_apx(float x) {
    float r;
    asm("tanh.approx.f32 %0, %1;" : "=f"(r) : "f"(x));
    return r;
}

__device__ __forceinline__ uint32_t smem_u32(const void* p) {
    uint32_t a;
    asm("{ .reg .u64 t; cvta.to.shared.u64 t, %1; cvt.u32.u64 %0, t; }" : "=r"(a) : "l"(p));
    return a;
}
__device__ __forceinline__ void mbar_init(uint32_t a, uint32_t cnt) {
    asm volatile("mbarrier.init.shared.b64 [%0], %1;" :: "r"(a), "r"(cnt) : "memory");
}
__device__ __forceinline__ void mbar_arrive_expect_tx(uint32_t a, uint32_t bytes) {
    asm volatile("mbarrier.arrive.expect_tx.shared.b64 _, [%0], %1;" :: "r"(a), "r"(bytes) : "memory");
}
__device__ __forceinline__ void mbar_wait(uint32_t a, uint32_t ph) {
    uint32_t done;
    asm volatile("{\n\t.reg .pred p;\n\t"
                 "mbarrier.try_wait.parity.acquire.cta.shared::cta.b64 p, [%1], %2;\n\t"
                 "selp.b32 %0, 1, 0, p;\n\t}"
                 : "=r"(done) : "r"(a), "r"(ph) : "memory");
    while (!done) {
        asm volatile("{\n\t.reg .pred p;\n\t"
                     "mbarrier.try_wait.parity.acquire.cta.shared::cta.b64 p, [%1], %2, 0x989680;\n\t"
                     "selp.b32 %0, 1, 0, p;\n\t}"
                     : "=r"(done) : "r"(a), "r"(ph) : "memory");
    }
}
__device__ __forceinline__ uint32_t mapa_sh(uint32_t local, uint32_t rank) {
    uint32_t r;
    asm("mapa.shared::cluster.u32 %0, %1, %2;" : "=r"(r) : "r"(local), "r"(rank));
    return r;
}
__device__ __forceinline__ void st_async_f32(uint32_t raddr, float v, uint32_t rmbar) {
    asm volatile("st.async.shared::cluster.mbarrier::complete_tx::bytes.b32 [%0], %1, [%2];"
                 :: "r"(raddr), "f"(v), "r"(rmbar) : "memory");
}

// ---- A: embedding gather + zx = emb@Wk + b (both dirs) ----
__global__ void k_pre(const int* __restrict__ sentence, const float* __restrict__ E,
                      const float* __restrict__ Wk_f, const float* __restrict__ b_f,
                      const float* __restrict__ Wk_b, const float* __restrict__ b_b) {
    __shared__ int   sent[TTP];
    __shared__ float emb[TTP][D];
    const int t0 = blockIdx.x * TTP, tid = threadIdx.x;
    if (tid < TTP) sent[tid] = sentence[t0 + tid];
    __syncthreads();
    for (int i = tid; i < TTP * D; i += blockDim.x)
        emb[i / D][i % D] = E[(long)sent[i / D] * D + (i % D)];
    __syncthreads();

    for (int dir = 0; dir < 2; dir++) {
        const float* Wk = dir ? Wk_b : Wk_f;
        const float* b  = dir ? b_b  : b_f;
        float* zx = dir ? g_zx_b : g_zx_f;
        for (int j = tid; j < G4; j += blockDim.x) {
            float acc[TTP];
#pragma unroll
            for (int tt = 0; tt < TTP; tt++) acc[tt] = b[j];
            for (int d = 0; d < D; d += 4) {
                float w0 = Wk[(d + 0) * G4 + j], w1 = Wk[(d + 1) * G4 + j];
                float w2 = Wk[(d + 2) * G4 + j], w3 = Wk[(d + 3) * G4 + j];
#pragma unroll
                for (int tt = 0; tt < TTP; tt++) {
                    float4 e4 = *(const float4*)&emb[tt][d];
                    acc[tt] += w0 * e4.x + w1 * e4.y + w2 * e4.z + w3 * e4.w;
                }
            }
#pragma unroll
            for (int tt = 0; tt < TTP; tt++) zx[(t0 + tt) * G4 + j] = acc[tt];
        }
    }
}

// ---- B: 10-CTA-cluster LSTM. Gate group on warps 6-7 (hi-wid arbiter priority).
// 256 threads = 4 k-quarters (tid>>6) x 64 threads. Quarter q covers k-rows
// [40q, 40q+40). Quarter 3 is the gate group: lane gate = l>>3, uu = l&7,
// ul = wq*8+uu (active if < 15). After the in-warp shfl combine, ALL 4 gate
// lanes of a unit compute (c,h) redundantly and each sends h to <=3 remote
// CTAs (destination split) -> st.async issue parallelized across lanes.
__global__ void __cluster_dims__(CS, 1, 1) __launch_bounds__(256, 1)
k_lstm_cl(const float* __restrict__ Wr_f, const float* __restrict__ Wr_b) {
    __shared__ __align__(16) float hbuf[2][4 * KQ];   // 160 floats (150 + 10 zero pad)
    __shared__ float zpart[3][64];
    __shared__ __align__(8) unsigned long long mbar[2];

    const int tid  = threadIdx.x;
    const int dir  = blockIdx.x / CS;
    const int rank = blockIdx.x % CS;
    const float* Wr = dir ? Wr_b : Wr_f;
    const float* zx = dir ? g_zx_b : g_zx_f;

    const uint32_t mb0 = smem_u32(&mbar[0]);
    const uint32_t mb1 = smem_u32(&mbar[1]);
    const uint32_t hb0 = smem_u32(&hbuf[0][0]);
    const uint32_t hb1 = smem_u32(&hbuf[1][0]);

    for (int i = tid; i < 2 * 4 * KQ; i += 256) ((float*)hbuf)[i] = 0.0f;
    if (tid == 0) { mbar_init(mb0, 1); mbar_init(mb1, 1); }
    __syncthreads();
    asm volatile("barrier.cluster.arrive.aligned;" ::: "memory");
    asm volatile("barrier.cluster.wait.aligned;"   ::: "memory");

    const int  quarter = tid >> 6;           // k-range quarter 0..3
    const int  q64  = tid & 63;
    const int  lane = tid & 31;
    const int  wq   = (tid >> 5) & 1;        // warp within quarter
    const int  gate = lane >> 3;             // 0..3
    const int  uu   = lane & 7;
    const int  ul   = wq * 8 + uu;           // local unit 0..15 (active if <15)
    const bool act  = ul < UPC;
    const int  jglob = gate * U + rank * UPC + ul;   // valid if act
    const bool is_tanh_gate = (gate == 2);
    const int  kbase = quarter * KQ;
    const bool gate_grp = (quarter == 3);    // warps 6,7: highest arbiter priority

    float w[KQ];
#pragma unroll
    for (int q = 0; q < KQ; q++) w[q] = 0.0f;
    if (act) {
#pragma unroll
        for (int q = 0; q < KQ; q++) {
            int kk = kbase + q;
            if (kk < U) w[q] = Wr[kk * G4 + jglob];
        }
    }

    // destination split: gate lane g covers ranks g*3 .. g*3+2 (g=3 -> rank 9 only)
    float c = 0.0f;
    uint32_t r_h0[3], r_h1[3], r_m0[3], r_m1[3];
    int ndst = 0;
    if (gate_grp && act) {
        const uint32_t uoff = (uint32_t)((rank * UPC + ul) * 4);
#pragma unroll
        for (int i = 0; i < 3; i++) {
            int r = gate * 3 + i;
            if (r < CS) {
                r_h0[ndst] = mapa_sh(hb0 + uoff, r);
                r_h1[ndst] = mapa_sh(hb1 + uoff, r);
                r_m0[ndst] = mapa_sh(mb0, r);
                r_m1[ndst] = mapa_sh(mb1, r);
                ndst++;
            }
        }
    }

    float zxv = (gate_grp && act) ? zx[(dir ? (SEQ - 1) : 0) * G4 + jglob] : 0.0f;

    for (int step = 0; step < SEQ; step++) {
        const int t = dir ? (SEQ - 1 - step) : step;

        if (step > 0) mbar_wait((step - 1) & 1 ? mb1 : mb0, ((step - 1) >> 1) & 1);
        if (tid == 0) mbar_arrive_expect_tx(step & 1 ? mb1 : mb0, CS * UPC * 4);

        const float4* h4 = (const float4*)(&hbuf[(step - 1) & 1][0] + kbase);
        float a0 = 0.f, a1 = 0.f, a2 = 0.f, a3 = 0.f;
#pragma unroll
        for (int q = 0; q < KQ / 4; q++) {
            float4 h = h4[q];
            a0 += w[4 * q + 0] * h.x; a1 += w[4 * q + 1] * h.y;
            a2 += w[4 * q + 2] * h.z; a3 += w[4 * q + 3] * h.w;
        }
        float partial = (a0 + a1) + (a2 + a3);
        if (!gate_grp) zpart[quarter][q64] = partial;

        float zx_next = 0.0f;
        if (gate_grp && act && step + 1 < SEQ) {
            int tn = dir ? (SEQ - 2 - step) : (step + 1);
            zx_next = zx[tn * G4 + jglob];
        }
        __syncthreads();   // zparts visible; quarters 0-2 run ahead to next mbar_wait

        if (gate_grp) {
            float z = zxv + partial + zpart[0][q64] + zpart[1][q64] + zpart[2][q64];
            // sigmoid(z) = 0.5 + 0.5*tanh(0.5z); cell gate uses tanh directly
            float targ = is_tanh_gate ? z : (0.5f * z);
            float tv   = tanh_apx(targ);
            float a    = is_tanh_gate ? tv : (0.5f + 0.5f * tv);

            // in-warp gate combine: unit uu's gates at lanes uu, 8+uu, 16+uu, 24+uu
            float ig = __shfl_sync(0xffffffffu, a, uu);
            float fg = __shfl_sync(0xffffffffu, a, 8 + uu);
            float gg = __shfl_sync(0xffffffffu, a, 16 + uu);
            float og = __shfl_sync(0xffffffffu, a, 24 + uu);

            if (act) {
                // all 4 gate lanes compute identical (c,h); each sends its dest slice
                c = fg * c + ig * gg;
                float h = og * tanh_apx(c);
                if (step & 1) {
                    for (int i = 0; i < ndst; i++) st_async_f32(r_h1[i], h, r_m1[i]);
                } else {
                    for (int i = 0; i < ndst; i++) st_async_f32(r_h0[i], h, r_m0[i]);
                }
                if (gate == 0) g_hidden[t * H1 + dir * U + rank * UPC + ul] = h;
            }
        }
        zxv = zx_next;
    }

    mbar_wait(mb1, ((SEQ - 1) >> 1) & 1);
    __syncthreads();
    asm volatile("barrier.cluster.arrive.aligned;" ::: "memory");
    asm volatile("barrier.cluster.wait.aligned;"   ::: "memory");
}

// ---- C: out = hidden @ W1 + b1 ----
__global__ void k_outk(const float* __restrict__ W1, const float* __restrict__ b1) {
    __shared__ float hid[TT][H1];
    const int t0 = blockIdx.x * TT, tid = threadIdx.x;
    for (int i = tid; i < TT * H1; i += blockDim.x) hid[i / H1][i % H1] = g_hidden[t0 * H1 + i];
    __syncthreads();
    for (int j = tid; j < H1; j += blockDim.x) {
        float acc[TT];
#pragma unroll
        for (int tt = 0; tt < TT; tt++) acc[tt] = b1[j];
        for (int d = 0; d < H1; d += 4) {
            float w0 = W1[(d + 0) * H1 + j], w1 = W1[(d + 1) * H1 + j];
            float w2 = W1[(d + 2) * H1 + j], w3 = W1[(d + 3) * H1 + j];
#pragma unroll
            for (int tt = 0; tt < TT; tt++) {
                float4 h4 = *(const float4*)&hid[tt][d];
                acc[tt] += w0 * h4.x + w1 * h4.y + w2 * h4.z + w3 * h4.w;
            }
        }
#pragma unroll
        for (int tt = 0; tt < TT; tt++) g_out[(t0 + tt) * H1 + j] = acc[tt];
    }
}

// ---- D: synonym attention; writes h_hat and c2 ----
__global__ void k_attn(const int* __restrict__ sentence, const int* __restrict__ syn,
                       const float* __restrict__ E, const float* __restrict__ W2,
                       const float* __restrict__ b2) {
    const int s = blockIdx.x, tid = threadIdx.x;
    const int lane = tid & 31, warp = tid >> 5;
    __shared__ int   rows[NSYN];
    __shared__ float red[4 * NSYN], redv[4], coef[NSYN];
    const int idx_s = (s == 0) ? 0 : (s - 1);
    if (tid < NSYN) rows[tid] = syn[(long)sentence[s] * NSYN + tid];
    __syncthreads();

    float ev[3][NSYN], hh[3];
    float p[NSYN] = {0.f, 0.f, 0.f, 0.f};
#pragma unroll
    for (int it = 0; it < 3; it++) {
        int d = tid + it * 128;
        if (d < H1) {
            float a = g_out[idx_s * H1 + d];
#pragma unroll
            for (int k = 0; k < NSYN; k++) { ev[it][k] = E[(long)rows[k] * D + d]; p[k] += ev[it][k] * a; }
        } else {
#pragma unroll
            for (int k = 0; k < NSYN; k++) ev[it][k] = 0.0f;
        }
    }
#pragma unroll
    for (int off = 16; off; off >>= 1)
#pragma unroll
        for (int k = 0; k < NSYN; k++) p[k] += __shfl_xor_sync(0xffffffffu, p[k], off);
    if (lane == 0)
#pragma unroll
        for (int k = 0; k < NSYN; k++) red[warp * NSYN + k] = p[k];
    __syncthreads();
    if (tid < NSYN)
        coef[tid] = expf(red[tid] + red[NSYN + tid] + red[2 * NSYN + tid] + red[3 * NSYN + tid]);
    __syncthreads();
    float c0 = coef[0], c1 = coef[1], c2c = coef[2], c3 = coef[3];

    float pv = 0.0f;
#pragma unroll
    for (int it = 0; it < 3; it++) {
        int d = tid + it * 128;
        if (d < H1) {
            float h = c0 * ev[it][0] + c1 * ev[it][1] + c2c * ev[it][2] + c3 * ev[it][3]
                    + g_hidden[idx_s * H1 + d];
            hh[it] = h;
            g_hhat[s * H1 + d] = h;
            pv += h * W2[d];
        } else hh[it] = 0.0f;
    }
#pragma unroll
    for (int off = 16; off; off >>= 1) pv += __shfl_xor_sync(0xffffffffu, pv, off);
    if (lane == 0) redv[warp] = pv;
    __syncthreads();
    if (tid == 0) {
        float v = redv[0] + redv[1] + redv[2] + redv[3] + b2[0];
        g_c2[s] = expf(tanhf(v));
    }
}

// ---- E: deterministic pooling ----
__global__ void k_pool() {
    const int d = blockIdx.x, tid = threadIdx.x;
    __shared__ float red[8];
    float acc = 0.0f;
    for (int s = tid; s < SEQ; s += blockDim.x) acc += g_c2[s] * g_hhat[s * H1 + d];
#pragma unroll
    for (int off = 16; off; off >>= 1) acc += __shfl_xor_sync(0xffffffffu, acc, off);
    if ((tid & 31) == 0) red[tid >> 5] = acc;
    __syncthreads();
    if (tid == 0) {
        float t = 0.0f;
#pragma unroll
        for (int w = 0; w < 8; w++) t += red[w];
        g_H[d] = t;
    }
}

// ---- F: heads -> d_out[0..8] ----
__global__ void k_final(const float* __restrict__ We, const float* __restrict__ be,
                        const float* __restrict__ Ws, const float* __restrict__ bs,
                        float* __restrict__ outp) {
    const int w = threadIdx.x >> 5, lane = threadIdx.x & 31;
    if (w >= 9) return;
    float acc = 0.0f;
    for (int d = lane; d < H1; d += 32)
        acc += g_H[d] * ((w < 8) ? We[d * 8 + w] : Ws[d]);
#pragma unroll
    for (int off = 16; off; off >>= 1) acc += __shfl_xor_sync(0xffffffffu, acc, off);
    if (lane == 0) outp[w] = acc + ((w < 8) ? be[w] : bs[0]);
}

extern "C" void kernel_launch(void* const* d_in, const int* in_sizes, int n_in,
                              void* d_out, int out_size) {
    const int*   sentence = (const int*)d_in[0];
    const int*   syn      = (const int*)d_in[1];
    const float* E        = (const float*)d_in[2];
    const float* Wk_f     = (const float*)d_in[3];
    const float* Wr_f     = (const float*)d_in[4];
    const float* b_f      = (const float*)d_in[5];
    const float* Wk_b     = (const float*)d_in[6];
    const float* Wr_b     = (const float*)d_in[7];
    const float* b_b      = (const float*)d_in[8];
    const float* W1       = (const float*)d_in[9];
    const float* b1       = (const float*)d_in[10];
    const float* W2       = (const float*)d_in[11];
    const float* b2       = (const float*)d_in[12];
    const float* We       = (const float*)d_in[13];
    const float* be       = (const float*)d_in[14];
    const float* Ws       = (const float*)d_in[15];
    const float* bs       = (const float*)d_in[16];
    float* outp = (float*)d_out;

    cudaFuncSetAttribute(k_lstm_cl, cudaFuncAttributeNonPortableClusterSizeAllowed, 1);

    k_pre    <<<SEQ / TTP, 256>>>(sentence, E, Wk_f, b_f, Wk_b, b_b);
    k_lstm_cl<<<2 * CS, 256>>>(Wr_f, Wr_b);
    k_outk   <<<SEQ / TT, 256>>>(W1, b1);
    k_attn   <<<SEQ, 128>>>(sentence, syn, E, W2, b2);
    k_pool   <<<H1, 256>>>();
    k_final  <<<1, 9 * 32>>>(We, be, Ws, bs, outp);
}

// round 11
// speedup vs baseline: 1.0346x; 1.0346x over previous
#include <cuda_runtime.h>
#include <cstdint>

#define SEQ  2048
#define D    300
#define U    150
#define G4   600
#define H1   300
#define NSYN 4
#define TT   8
#define TTP  16

#define CS   10    // cluster size (CTAs per direction)
#define UPC  15    // units per CTA
#define KQ   40    // k-rows per quarter (4*40 = 160 = 150 + 10 zero pad)

__device__ float g_zx_f[SEQ * G4];
__device__ float g_zx_b[SEQ * G4];
__device__ float g_hidden[SEQ * H1];
__device__ float g_out[SEQ * H1];
__device__ float g_hhat[SEQ * H1];
__device__ float g_c2[SEQ];
__device__ float g_H[H1];

__device__ __forceinline__ float tanh_apx(float x) {
    float r;
    asm("tanh.approx.f32 %0, %1;" : "=f"(r) : "f"(x));
    return r;
}

__device__ __forceinline__ uint32_t smem_u32(const void* p) {
    uint32_t a;
    asm("{ .reg .u64 t; cvta.to.shared.u64 t, %1; cvt.u32.u64 %0, t; }" : "=r"(a) : "l"(p));
    return a;
}
__device__ __forceinline__ void mbar_init(uint32_t a, uint32_t cnt) {
    asm volatile("mbarrier.init.shared.b64 [%0], %1;" :: "r"(a), "r"(cnt) : "memory");
}
__device__ __forceinline__ void mbar_arrive_expect_tx(uint32_t a, uint32_t bytes) {
    asm volatile("mbarrier.arrive.expect_tx.shared.b64 _, [%0], %1;" :: "r"(a), "r"(bytes) : "memory");
}
__device__ __forceinline__ void mbar_wait(uint32_t a, uint32_t ph) {
    uint32_t done;
    asm volatile("{\n\t.reg .pred p;\n\t"
                 "mbarrier.try_wait.parity.acquire.cta.shared::cta.b64 p, [%1], %2;\n\t"
                 "selp.b32 %0, 1, 0, p;\n\t}"
                 : "=r"(done) : "r"(a), "r"(ph) : "memory");
    while (!done) {
        asm volatile("{\n\t.reg .pred p;\n\t"
                     "mbarrier.try_wait.parity.acquire.cta.shared::cta.b64 p, [%1], %2, 0x989680;\n\t"
                     "selp.b32 %0, 1, 0, p;\n\t}"
                     : "=r"(done) : "r"(a), "r"(ph) : "memory");
    }
}
__device__ __forceinline__ uint32_t mapa_sh(uint32_t local, uint32_t rank) {
    uint32_t r;
    asm("mapa.shared::cluster.u32 %0, %1, %2;" : "=r"(r) : "r"(local), "r"(rank));
    return r;
}
__device__ __forceinline__ void st_async_f32(uint32_t raddr, float v, uint32_t rmbar) {
    asm volatile("st.async.shared::cluster.mbarrier::complete_tx::bytes.b32 [%0], %1, [%2];"
                 :: "r"(raddr), "f"(v), "r"(rmbar) : "memory");
}
// packed f32x2 helpers
__device__ __forceinline__ unsigned long long pk2(float a, float b) {
    unsigned long long r;
    asm("mov.b64 %0, {%1, %2};" : "=l"(r) : "f"(a), "f"(b));
    return r;
}
__device__ __forceinline__ void upk2(unsigned long long v, float& a, float& b) {
    asm("mov.b64 {%0, %1}, %2;" : "=f"(a), "=f"(b) : "l"(v));
}
__device__ __forceinline__ unsigned long long fma2(unsigned long long a, unsigned long long b,
                                                   unsigned long long c) {
    unsigned long long r;
    asm("fma.rn.f32x2 %0, %1, %2, %3;" : "=l"(r) : "l"(a), "l"(b), "l"(c));
    return r;
}

// ---- A: embedding gather + zx = emb@Wk + b (both dirs) ----
__global__ void k_pre(const int* __restrict__ sentence, const float* __restrict__ E,
                      const float* __restrict__ Wk_f, const float* __restrict__ b_f,
                      const float* __restrict__ Wk_b, const float* __restrict__ b_b) {
    __shared__ int   sent[TTP];
    __shared__ float emb[TTP][D];
    const int t0 = blockIdx.x * TTP, tid = threadIdx.x;
    if (tid < TTP) sent[tid] = sentence[t0 + tid];
    __syncthreads();
    for (int i = tid; i < TTP * D; i += blockDim.x)
        emb[i / D][i % D] = E[(long)sent[i / D] * D + (i % D)];
    __syncthreads();

    for (int dir = 0; dir < 2; dir++) {
        const float* Wk = dir ? Wk_b : Wk_f;
        const float* b  = dir ? b_b  : b_f;
        float* zx = dir ? g_zx_b : g_zx_f;
        for (int j = tid; j < G4; j += blockDim.x) {
            float acc[TTP];
#pragma unroll
            for (int tt = 0; tt < TTP; tt++) acc[tt] = b[j];
            for (int d = 0; d < D; d += 4) {
                float w0 = Wk[(d + 0) * G4 + j], w1 = Wk[(d + 1) * G4 + j];
                float w2 = Wk[(d + 2) * G4 + j], w3 = Wk[(d + 3) * G4 + j];
#pragma unroll
                for (int tt = 0; tt < TTP; tt++) {
                    float4 e4 = *(const float4*)&emb[tt][d];
                    acc[tt] += w0 * e4.x + w1 * e4.y + w2 * e4.z + w3 * e4.w;
                }
            }
#pragma unroll
            for (int tt = 0; tt < TTP; tt++) zx[(t0 + tt) * G4 + j] = acc[tt];
        }
    }
}

// ---- B: 10-CTA-cluster LSTM (R8 structure + f32x2 packed matvec) ----
// 256 threads = 4 k-quarters (tid>>6) x 64 threads; quarter q covers k-rows
// [40q, 40q+40). Quarter 0 holds the gate group (gate 0 lanes). Weights are
// packed u64 pairs; h read as double2 (16B broadcast LDS, conflict-free).
__global__ void __cluster_dims__(CS, 1, 1) __launch_bounds__(256, 1)
k_lstm_cl(const float* __restrict__ Wr_f, const float* __restrict__ Wr_b) {
    __shared__ __align__(16) float hbuf[2][4 * KQ];   // 160 floats (150 + 10 zero pad)
    __shared__ float zpart[3][64];
    __shared__ __align__(8) unsigned long long mbar[2];

    const int tid  = threadIdx.x;
    const int dir  = blockIdx.x / CS;
    const int rank = blockIdx.x % CS;
    const float* Wr = dir ? Wr_b : Wr_f;
    const float* zx = dir ? g_zx_b : g_zx_f;

    const uint32_t mb0 = smem_u32(&mbar[0]);
    const uint32_t mb1 = smem_u32(&mbar[1]);
    const uint32_t hb0 = smem_u32(&hbuf[0][0]);
    const uint32_t hb1 = smem_u32(&hbuf[1][0]);

    for (int i = tid; i < 2 * 4 * KQ; i += 256) ((float*)hbuf)[i] = 0.0f;
    if (tid == 0) { mbar_init(mb0, 1); mbar_init(mb1, 1); }
    __syncthreads();
    asm volatile("barrier.cluster.arrive.aligned;" ::: "memory");
    asm volatile("barrier.cluster.wait.aligned;"   ::: "memory");

    const int  quarter = tid >> 6;           // k-range quarter 0..3
    const int  q64  = tid & 63;
    const int  lane = tid & 31;
    const int  wq   = (tid >> 5) & 1;        // warp within quarter
    const int  gate = lane >> 3;             // 0..3
    const int  uu   = lane & 7;
    const int  ul   = wq * 8 + uu;           // local unit 0..15 (active if <15)
    const bool act  = ul < UPC;
    const int  jglob = gate * U + rank * UPC + ul;   // valid if act
    const bool is_tanh_gate = (gate == 2);
    const int  kbase = quarter * KQ;

    // packed weights: 20 u64 pairs covering 40 k-rows
    unsigned long long w2[KQ / 2];
#pragma unroll
    for (int q = 0; q < KQ / 2; q++) w2[q] = 0ull;
    if (act) {
#pragma unroll
        for (int q = 0; q < KQ / 2; q++) {
            int k0 = kbase + 2 * q, k1 = kbase + 2 * q + 1;
            float f0 = (k0 < U) ? Wr[k0 * G4 + jglob] : 0.0f;
            float f1 = (k1 < U) ? Wr[k1 * G4 + jglob] : 0.0f;
            w2[q] = pk2(f0, f1);
        }
    }

    const bool gate_lane = (quarter == 0) && (gate == 0) && act;
    float c = 0.0f;
    uint32_t r_h0[CS], r_h1[CS], r_m0[CS], r_m1[CS];
    if (gate_lane) {
        const uint32_t uoff = (uint32_t)((rank * UPC + ul) * 4);
#pragma unroll
        for (int r = 0; r < CS; r++) {
            r_h0[r] = mapa_sh(hb0 + uoff, r);
            r_h1[r] = mapa_sh(hb1 + uoff, r);
            r_m0[r] = mapa_sh(mb0, r);
            r_m1[r] = mapa_sh(mb1, r);
        }
    }

    float zxv = (act && quarter == 0) ? zx[(dir ? (SEQ - 1) : 0) * G4 + jglob] : 0.0f;

    for (int step = 0; step < SEQ; step++) {
        const int t = dir ? (SEQ - 1 - step) : step;

        if (step > 0) mbar_wait((step - 1) & 1 ? mb1 : mb0, ((step - 1) >> 1) & 1);
        if (tid == 192) mbar_arrive_expect_tx(step & 1 ? mb1 : mb0, CS * UPC * 4);

        const double2* h2 = (const double2*)(&hbuf[(step - 1) & 1][0] + kbase);
        unsigned long long acc0 = 0ull, acc1 = 0ull, acc2 = 0ull, acc3 = 0ull;
#pragma unroll
        for (int q = 0; q < KQ / 8; q++) {        // 5 iterations, 2 LDS.128 each
            double2 d0 = h2[2 * q], d1 = h2[2 * q + 1];
            acc0 = fma2(w2[4 * q + 0], (unsigned long long)__double_as_longlong(d0.x), acc0);
            acc1 = fma2(w2[4 * q + 1], (unsigned long long)__double_as_longlong(d0.y), acc1);
            acc2 = fma2(w2[4 * q + 2], (unsigned long long)__double_as_longlong(d1.x), acc2);
            acc3 = fma2(w2[4 * q + 3], (unsigned long long)__double_as_longlong(d1.y), acc3);
        }
        float x0, x1, y0, y1, u0, u1, v0, v1;
        upk2(acc0, x0, x1); upk2(acc1, y0, y1);
        upk2(acc2, u0, u1); upk2(acc3, v0, v1);
        float partial = ((x0 + x1) + (y0 + y1)) + ((u0 + u1) + (v0 + v1));
        if (quarter != 0) zpart[quarter - 1][q64] = partial;

        float zx_next = 0.0f;
        if (act && quarter == 0 && step + 1 < SEQ) {
            int tn = dir ? (SEQ - 2 - step) : (step + 1);
            zx_next = zx[tn * G4 + jglob];
        }
        __syncthreads();   // zparts visible; quarters 1-3 run ahead to next mbar_wait

        if (quarter == 0) {
            float z = zxv + partial + zpart[0][q64] + zpart[1][q64] + zpart[2][q64];
            // sigmoid(z) = 0.5 + 0.5*tanh(0.5z); cell gate uses tanh directly
            float targ = is_tanh_gate ? z : (0.5f * z);
            float tv   = tanh_apx(targ);
            float a    = is_tanh_gate ? tv : (0.5f + 0.5f * tv);

            // in-warp gate combine: unit uu's gates at lanes uu, 8+uu, 16+uu, 24+uu
            float ig = __shfl_sync(0xffffffffu, a, uu);
            float fg = __shfl_sync(0xffffffffu, a, 8 + uu);
            float gg = __shfl_sync(0xffffffffu, a, 16 + uu);
            float og = __shfl_sync(0xffffffffu, a, 24 + uu);

            if (gate_lane) {
                c = fg * c + ig * gg;
                float h = og * tanh_apx(c);
                if (step & 1) {
#pragma unroll
                    for (int r = 0; r < CS; r++) st_async_f32(r_h1[r], h, r_m1[r]);
                } else {
#pragma unroll
                    for (int r = 0; r < CS; r++) st_async_f32(r_h0[r], h, r_m0[r]);
                }
                g_hidden[t * H1 + dir * U + rank * UPC + ul] = h;
            }
        }
        zxv = zx_next;
    }

    mbar_wait(mb1, ((SEQ - 1) >> 1) & 1);
    __syncthreads();
    asm volatile("barrier.cluster.arrive.aligned;" ::: "memory");
    asm volatile("barrier.cluster.wait.aligned;"   ::: "memory");
}

// ---- C: out = hidden @ W1 + b1 ----
__global__ void k_outk(const float* __restrict__ W1, const float* __restrict__ b1) {
    __shared__ float hid[TT][H1];
    const int t0 = blockIdx.x * TT, tid = threadIdx.x;
    for (int i = tid; i < TT * H1; i += blockDim.x) hid[i / H1][i % H1] = g_hidden[t0 * H1 + i];
    __syncthreads();
    for (int j = tid; j < H1; j += blockDim.x) {
        float acc[TT];
#pragma unroll
        for (int tt = 0; tt < TT; tt++) acc[tt] = b1[j];
        for (int d = 0; d < H1; d += 4) {
            float w0 = W1[(d + 0) * H1 + j], w1 = W1[(d + 1) * H1 + j];
            float w2 = W1[(d + 2) * H1 + j], w3 = W1[(d + 3) * H1 + j];
#pragma unroll
            for (int tt = 0; tt < TT; tt++) {
                float4 h4 = *(const float4*)&hid[tt][d];
                acc[tt] += w0 * h4.x + w1 * h4.y + w2 * h4.z + w3 * h4.w;
            }
        }
#pragma unroll
        for (int tt = 0; tt < TT; tt++) g_out[(t0 + tt) * H1 + j] = acc[tt];
    }
}

// ---- D: synonym attention; writes h_hat and c2 ----
__global__ void k_attn(const int* __restrict__ sentence, const int* __restrict__ syn,
                       const float* __restrict__ E, const float* __restrict__ W2,
                       const float* __restrict__ b2) {
    const int s = blockIdx.x, tid = threadIdx.x;
    const int lane = tid & 31, warp = tid >> 5;
    __shared__ int   rows[NSYN];
    __shared__ float red[4 * NSYN], redv[4], coef[NSYN];
    const int idx_s = (s == 0) ? 0 : (s - 1);
    if (tid < NSYN) rows[tid] = syn[(long)sentence[s] * NSYN + tid];
    __syncthreads();

    float ev[3][NSYN], hh[3];
    float p[NSYN] = {0.f, 0.f, 0.f, 0.f};
#pragma unroll
    for (int it = 0; it < 3; it++) {
        int d = tid + it * 128;
        if (d < H1) {
            float a = g_out[idx_s * H1 + d];
#pragma unroll
            for (int k = 0; k < NSYN; k++) { ev[it][k] = E[(long)rows[k] * D + d]; p[k] += ev[it][k] * a; }
        } else {
#pragma unroll
            for (int k = 0; k < NSYN; k++) ev[it][k] = 0.0f;
        }
    }
#pragma unroll
    for (int off = 16; off; off >>= 1)
#pragma unroll
        for (int k = 0; k < NSYN; k++) p[k] += __shfl_xor_sync(0xffffffffu, p[k], off);
    if (lane == 0)
#pragma unroll
        for (int k = 0; k < NSYN; k++) red[warp * NSYN + k] = p[k];
    __syncthreads();
    if (tid < NSYN)
        coef[tid] = expf(red[tid] + red[NSYN + tid] + red[2 * NSYN + tid] + red[3 * NSYN + tid]);
    __syncthreads();
    float c0 = coef[0], c1 = coef[1], c2c = coef[2], c3 = coef[3];

    float pv = 0.0f;
#pragma unroll
    for (int it = 0; it < 3; it++) {
        int d = tid + it * 128;
        if (d < H1) {
            float h = c0 * ev[it][0] + c1 * ev[it][1] + c2c * ev[it][2] + c3 * ev[it][3]
                    + g_hidden[idx_s * H1 + d];
            hh[it] = h;
            g_hhat[s * H1 + d] = h;
            pv += h * W2[d];
        } else hh[it] = 0.0f;
    }
#pragma unroll
    for (int off = 16; off; off >>= 1) pv += __shfl_xor_sync(0xffffffffu, pv, off);
    if (lane == 0) redv[warp] = pv;
    __syncthreads();
    if (tid == 0) {
        float v = redv[0] + redv[1] + redv[2] + redv[3] + b2[0];
        g_c2[s] = expf(tanhf(v));
    }
}

// ---- E: deterministic pooling ----
__global__ void k_pool() {
    const int d = blockIdx.x, tid = threadIdx.x;
    __shared__ float red[8];
    float acc = 0.0f;
    for (int s = tid; s < SEQ; s += blockDim.x) acc += g_c2[s] * g_hhat[s * H1 + d];
#pragma unroll
    for (int off = 16; off; off >>= 1) acc += __shfl_xor_sync(0xffffffffu, acc, off);
    if ((tid & 31) == 0) red[tid >> 5] = acc;
    __syncthreads();
    if (tid == 0) {
        float t = 0.0f;
#pragma unroll
        for (int w = 0; w < 8; w++) t += red[w];
        g_H[d] = t;
    }
}

// ---- F: heads -> d_out[0..8] ----
__global__ void k_final(const float* __restrict__ We, const float* __restrict__ be,
                        const float* __restrict__ Ws, const float* __restrict__ bs,
                        float* __restrict__ outp) {
    const int w = threadIdx.x >> 5, lane = threadIdx.x & 31;
    if (w >= 9) return;
    float acc = 0.0f;
    for (int d = lane; d < H1; d += 32)
        acc += g_H[d] * ((w < 8) ? We[d * 8 + w] : Ws[d]);
#pragma unroll
    for (int off = 16; off; off >>= 1) acc += __shfl_xor_sync(0xffffffffu, acc, off);
    if (lane == 0) outp[w] = acc + ((w < 8) ? be[w] : bs[0]);
}

extern "C" void kernel_launch(void* const* d_in, const int* in_sizes, int n_in,
                              void* d_out, int out_size) {
    const int*   sentence = (const int*)d_in[0];
    const int*   syn      = (const int*)d_in[1];
    const float* E        = (const float*)d_in[2];
    const float* Wk_f     = (const float*)d_in[3];
    const float* Wr_f     = (const float*)d_in[4];
    const float* b_f      = (const float*)d_in[5];
    const float* Wk_b     = (const float*)d_in[6];
    const float* Wr_b     = (const float*)d_in[7];
    const float* b_b      = (const float*)d_in[8];
    const float* W1       = (const float*)d_in[9];
    const float* b1       = (const float*)d_in[10];
    const float* W2       = (const float*)d_in[11];
    const float* b2       = (const float*)d_in[12];
    const float* We       = (const float*)d_in[13];
    const float* be       = (const float*)d_in[14];
    const float* Ws       = (const float*)d_in[15];
    const float* bs       = (const float*)d_in[16];
    float* outp = (float*)d_out;

    cudaFuncSetAttribute(k_lstm_cl, cudaFuncAttributeNonPortableClusterSizeAllowed, 1);

    k_pre    <<<SEQ / TTP, 256>>>(sentence, E, Wk_f, b_f, Wk_b, b_b);
    k_lstm_cl<<<2 * CS, 256>>>(Wr_f, Wr_b);
    k_outk   <<<SEQ / TT, 256>>>(W1, b1);
    k_attn   <<<SEQ, 128>>>(sentence, syn, E, W2, b2);
    k_pool   <<<H1, 256>>>();
    k_final  <<<1, 9 * 32>>>(We, be, Ws, bs, outp);
}